// round 2
// baseline (speedup 1.0000x reference)
#include <cuda_runtime.h>

#define NN 100000
#define EE 1000000
#define ET (EE + NN)          // edges + self loops
#define HC 128                // H*C
#define CC 64
#define EPS 1e-5f
#define SLOPE 0.2f

// ---------------- scratch (device globals; no allocation allowed) ----------------
__device__ float4 g_h[NN * 32];      // h: (N, H*C) as float4[32]/node   51.2MB
__device__ float4 g_acc[NN * 32];    // msg accumulator (N,H,C)         51.2MB
__device__ float  g_as[NN * 2];      // per-node per-head attention src
__device__ float  g_ad[NN * 2];
__device__ unsigned g_mx[NN * 2];    // segment max (flipped-float keys)
__device__ float  g_sm[NN * 2];      // segment sum of exp
__device__ float  g_hm[NN * CC];     // head-mean (pre-BN)              25.6MB
__device__ float  g_x[NN * CC];      // BN+relu output -> next layer    25.6MB
__device__ double g_cs[CC], g_css[CC];
__device__ float  g_scale[CC], g_shift[CC];

// ---------------- helpers ----------------
__device__ __forceinline__ unsigned flip_f(float v) {
    unsigned u = __float_as_uint(v);
    return (u & 0x80000000u) ? ~u : (u | 0x80000000u);
}
__device__ __forceinline__ float unflip_f(unsigned u) {
    u = (u & 0x80000000u) ? (u & 0x7fffffffu) : ~u;
    return __uint_as_float(u);
}
__device__ __forceinline__ float lrelu(float v) { return v > 0.f ? v : SLOPE * v; }

// ---------------- zero scratch (runs each layer) ----------------
__global__ void zero_kernel() {
    int i = blockIdx.x * blockDim.x + threadIdx.x;
    int stride = gridDim.x * blockDim.x;
    float4 z = make_float4(0.f, 0.f, 0.f, 0.f);
    for (int k = i; k < NN * 32; k += stride) g_acc[k] = z;
    for (int k = i; k < NN * 2; k += stride) { g_mx[k] = 0u; g_sm[k] = 0.f; }
    if (i < CC) { g_cs[i] = 0.0; g_css[i] = 0.0; }
}

// ---------------- linear: h = x @ W, plus a_s, a_d per node/head ----------------
// block = 128 threads (one node), thread j computes h[n, j]
__global__ void lin_kernel(const float* __restrict__ xext,
                           const float* __restrict__ W,
                           const float* __restrict__ att_s,
                           const float* __restrict__ att_d,
                           int din, int use_internal) {
    int n = blockIdx.x;
    int j = threadIdx.x;
    __shared__ float xs[64];
    __shared__ float ps[4], pd[4];
    const float* xin = use_internal ? (const float*)g_x : xext;
    if (j < din) xs[j] = xin[n * din + j];
    __syncthreads();
    float acc = 0.f;
#pragma unroll 8
    for (int k = 0; k < din; k++) acc = fmaf(xs[k], W[k * HC + j], acc);
    ((float*)g_h)[n * HC + j] = acc;
    float vs = acc * att_s[j];
    float vd = acc * att_d[j];
#pragma unroll
    for (int o = 16; o; o >>= 1) {
        vs += __shfl_down_sync(0xffffffffu, vs, o);
        vd += __shfl_down_sync(0xffffffffu, vd, o);
    }
    int w = j >> 5;
    if ((j & 31) == 0) { ps[w] = vs; pd[w] = vd; }
    __syncthreads();
    if (j == 0)  { g_as[n * 2 + 0] = ps[0] + ps[1]; g_ad[n * 2 + 0] = pd[0] + pd[1]; }
    if (j == 64) { g_as[n * 2 + 1] = ps[2] + ps[3]; g_ad[n * 2 + 1] = pd[2] + pd[3]; }
}

// ---------------- edge pass A: segment max ----------------
__global__ void edge_max_kernel(const int* __restrict__ src, const int* __restrict__ dst) {
    int t = blockIdx.x * blockDim.x + threadIdx.x;
    if (t >= 2 * ET) return;
    int e = t >> 1, h = t & 1;
    int s, d;
    if (e < EE) { s = src[e]; d = dst[e]; } else { s = d = e - EE; }
    float v = lrelu(g_as[s * 2 + h] + g_ad[d * 2 + h]);
    atomicMax(&g_mx[d * 2 + h], flip_f(v));
}

// ---------------- edge pass B: segment sum of exp ----------------
__global__ void edge_sum_kernel(const int* __restrict__ src, const int* __restrict__ dst) {
    int t = blockIdx.x * blockDim.x + threadIdx.x;
    if (t >= 2 * ET) return;
    int e = t >> 1, h = t & 1;
    int s, d;
    if (e < EE) { s = src[e]; d = dst[e]; } else { s = d = e - EE; }
    float v = lrelu(g_as[s * 2 + h] + g_ad[d * 2 + h]);
    float m = unflip_f(g_mx[d * 2 + h]);
    atomicAdd(&g_sm[d * 2 + h], __expf(v - m));
}

// ---------------- edge pass C: weighted message scatter ----------------
// one warp per edge; lane -> float4 chunk of (H,C)=128 floats
__global__ void edge_msg_kernel(const int* __restrict__ src, const int* __restrict__ dst) {
    int gt = blockIdx.x * blockDim.x + threadIdx.x;
    int e = gt >> 5;
    int lane = gt & 31;
    if (e >= ET) return;
    int s, d;
    if (e < EE) { s = src[e]; d = dst[e]; } else { s = d = e - EE; }
    int h = lane >> 4;
    float v = lrelu(g_as[s * 2 + h] + g_ad[d * 2 + h]);
    float m = unflip_f(g_mx[d * 2 + h]);
    float sum = g_sm[d * 2 + h];
    float alpha = __expf(v - m) / (sum + 1e-16f);
    float4 hv = g_h[s * 32 + lane];
    float4 r = make_float4(alpha * hv.x, alpha * hv.y, alpha * hv.z, alpha * hv.w);
#if __CUDA_ARCH__ >= 900
    atomicAdd(&g_acc[d * 32 + lane], r);
#else
    float* a = (float*)&g_acc[d * 32 + lane];
    atomicAdd(a + 0, r.x); atomicAdd(a + 1, r.y);
    atomicAdd(a + 2, r.z); atomicAdd(a + 3, r.w);
#endif
}

// ---------------- BN stats: head mean + bias, channel sums ----------------
// block = 256 = 4 node-rows x 64 channels
__global__ void bn_stats_kernel(const float* __restrict__ bias) {
    int c = threadIdx.x & 63;
    int r = threadIdx.x >> 6;
    float s1 = 0.f, s2 = 0.f;
    const float* acc = (const float*)g_acc;
    for (int n = blockIdx.x * 4 + r; n < NN; n += gridDim.x * 4) {
        float v = 0.5f * (acc[n * 128 + c] + acc[n * 128 + 64 + c]) + bias[c];
        g_hm[n * 64 + c] = v;
        s1 += v; s2 += v * v;
    }
    __shared__ float sh1[256], sh2[256];
    sh1[threadIdx.x] = s1; sh2[threadIdx.x] = s2;
    __syncthreads();
    if (r == 0) {
        s1 = sh1[c] + sh1[64 + c] + sh1[128 + c] + sh1[192 + c];
        s2 = sh2[c] + sh2[64 + c] + sh2[128 + c] + sh2[192 + c];
        atomicAdd(&g_cs[c], (double)s1);
        atomicAdd(&g_css[c], (double)s2);
    }
}

__global__ void bn_fin_kernel(const float* __restrict__ gw, const float* __restrict__ be) {
    int c = threadIdx.x;
    float m = (float)(g_cs[c] / (double)NN);
    float var = (float)(g_css[c] / (double)NN) - m * m;
    var = fmaxf(var, 0.f);
    float rs = rsqrtf(var + EPS);
    float sc = rs * gw[c];
    g_scale[c] = sc;
    g_shift[c] = be[c] - m * sc;
}

__global__ void bn_apply_kernel() {
    int i = blockIdx.x * blockDim.x + threadIdx.x;
    if (i >= NN * CC) return;
    int c = i & 63;
    float y = g_hm[i] * g_scale[c] + g_shift[c];
    g_x[i] = y > 0.f ? y : 0.f;
}

// ---------------- MLP heads ----------------
// block = 64 threads (one node)
__global__ void mlp_kernel(const float* __restrict__ x0,
                           const float* __restrict__ mW1, const float* __restrict__ mb1,
                           const float* __restrict__ mW2, const float* __restrict__ mb2,
                           const float* __restrict__ pW, const float* __restrict__ pb,
                           const float* __restrict__ vW, const float* __restrict__ vb,
                           float* __restrict__ out) {
    int n = blockIdx.x;
    int j = threadIdx.x;
    __shared__ float hc[72];
    __shared__ float h1[64];
    __shared__ float pl[2], pv[2];
    hc[j] = g_x[n * 64 + j];
    if (j < 5) hc[64 + j] = x0[n * 16 + 9 + j];
    __syncthreads();
    float a = mb1[j];
#pragma unroll
    for (int k = 0; k < 69; k++) a = fmaf(hc[k], mW1[k * 64 + j], a);
    a = a > 0.f ? a : 0.f;
    h1[j] = a;
    __syncthreads();
    float b = mb2[j];
#pragma unroll
    for (int k = 0; k < 64; k++) b = fmaf(h1[k], mW2[k * 64 + j], b);
    float lg = b * pW[j];
    float vl = b * vW[j];
#pragma unroll
    for (int o = 16; o; o >>= 1) {
        lg += __shfl_down_sync(0xffffffffu, lg, o);
        vl += __shfl_down_sync(0xffffffffu, vl, o);
    }
    int w = j >> 5;
    if ((j & 31) == 0) { pl[w] = lg; pv[w] = vl; }
    __syncthreads();
    if (j == 0) {
        out[n]      = pl[0] + pl[1] + pb[0];
        out[NN + n] = pv[0] + pv[1] + vb[0];
    }
}

// ---------------- launch ----------------
extern "C" void kernel_launch(void* const* d_in, const int* in_sizes, int n_in,
                              void* d_out, int out_size) {
    const float* x   = (const float*)d_in[0];
    const int*   ei  = (const int*)d_in[1];
    const int*   src = ei;
    const int*   dst = ei + EE;
    float* out = (float*)d_out;

    // layer params: W, as, ad, b, g, be at indices 2.., 8.., 14..
    const int base[3] = {2, 8, 14};
    const int din[3]  = {16, 64, 64};

    for (int l = 0; l < 3; l++) {
        const float* W   = (const float*)d_in[base[l] + 0];
        const float* as_ = (const float*)d_in[base[l] + 1];
        const float* ad_ = (const float*)d_in[base[l] + 2];
        const float* b_  = (const float*)d_in[base[l] + 3];
        const float* g_  = (const float*)d_in[base[l] + 4];
        const float* be_ = (const float*)d_in[base[l] + 5];

        zero_kernel<<<2048, 256>>>();
        lin_kernel<<<NN, 128>>>(x, W, as_, ad_, din[l], l > 0 ? 1 : 0);
        int eb = (2 * ET + 255) / 256;
        edge_max_kernel<<<eb, 256>>>(src, dst);
        edge_sum_kernel<<<eb, 256>>>(src, dst);
        int mb = (ET * 32 + 255) / 256;
        edge_msg_kernel<<<mb, 256>>>(src, dst);
        bn_stats_kernel<<<1184, 256>>>(b_);
        bn_fin_kernel<<<1, 64>>>(g_, be_);
        bn_apply_kernel<<<(NN * CC + 255) / 256, 256>>>();
    }

    const float* mW1 = (const float*)d_in[20];
    const float* mb1 = (const float*)d_in[21];
    const float* mW2 = (const float*)d_in[22];
    const float* mb2 = (const float*)d_in[23];
    const float* pW  = (const float*)d_in[24];
    const float* pb  = (const float*)d_in[25];
    const float* vW  = (const float*)d_in[26];
    const float* vb  = (const float*)d_in[27];
    mlp_kernel<<<NN, 64>>>(x, mW1, mb1, mW2, mb2, pW, pb, vW, vb, out);
}

// round 4
// speedup vs baseline: 2.2885x; 2.2885x over previous
#include <cuda_runtime.h>

#define NN 100000
#define EE 1000000
#define ET (EE + NN)          // edges + self loops
#define HC 128                // H*C
#define CC 64
#define EPS 1e-5f
#define SLOPE 0.2f
#define NB1 ((NN + 1023) / 1024)   // 98 scan blocks

// ---------------- scratch (device globals) ----------------
__device__ float4 g_h[NN * 32];      // h: (N, H*C) as float4[32]/node   51.2MB
__device__ float  g_as[NN * 2];      // per-node per-head attention src score
__device__ float  g_ad[NN * 2];
__device__ float  g_hm[NN * CC];     // head-mean (pre-BN affine)       25.6MB
__device__ double g_cs[CC], g_css[CC];
__device__ float  g_scale[CC], g_shift[CC];
// CSR
__device__ int    g_cnt[NN];
__device__ int    g_row[NN + 1];
__device__ int    g_cur[NN];
__device__ int    g_srt[ET];         // src ids sorted by dst
__device__ int    g_bsum[128];

__device__ __forceinline__ float lrelu(float v) { return v > 0.f ? v : SLOPE * v; }

// ==================== CSR build ====================
__global__ void zero_cnt_kernel() {
    int i = blockIdx.x * blockDim.x + threadIdx.x;
    if (i < NN) g_cnt[i] = 0;
}

__global__ void hist_kernel(const int* __restrict__ dst) {
    int t = blockIdx.x * blockDim.x + threadIdx.x;
    if (t >= ET) return;
    int d = (t < EE) ? dst[t] : t - EE;
    atomicAdd(&g_cnt[d], 1);
}

__global__ void scan1_kernel() {
    int i = blockIdx.x * 1024 + threadIdx.x;
    int v = (i < NN) ? g_cnt[i] : 0;
    __shared__ int sh[1024];
    sh[threadIdx.x] = v;
    __syncthreads();
    for (int o = 1; o < 1024; o <<= 1) {
        int t = (threadIdx.x >= o) ? sh[threadIdx.x - o] : 0;
        __syncthreads();
        sh[threadIdx.x] += t;
        __syncthreads();
    }
    if (i < NN) g_row[i] = sh[threadIdx.x] - v;     // exclusive
    if (threadIdx.x == 1023) g_bsum[blockIdx.x] = sh[1023];
}

__global__ void scan2_kernel() {
    int i = threadIdx.x;                            // 128 threads
    int v = (i < NB1) ? g_bsum[i] : 0;
    __shared__ int sh[128];
    sh[i] = v;
    __syncthreads();
    for (int o = 1; o < 128; o <<= 1) {
        int t = (i >= o) ? sh[i - o] : 0;
        __syncthreads();
        sh[i] += t;
        __syncthreads();
    }
    if (i < NB1) g_bsum[i] = sh[i] - v;             // exclusive
}

__global__ void scan3_kernel() {
    int i = blockIdx.x * blockDim.x + threadIdx.x;
    if (i < NN) {
        int r = g_row[i] + g_bsum[i >> 10];
        g_row[i] = r;
        g_cur[i] = r;
    }
    if (i == 0) g_row[NN] = ET;
}

__global__ void scatter_kernel(const int* __restrict__ src, const int* __restrict__ dst) {
    int t = blockIdx.x * blockDim.x + threadIdx.x;
    if (t >= ET) return;
    int s, d;
    if (t < EE) { s = src[t]; d = dst[t]; } else { s = d = t - EE; }
    int pos = atomicAdd(&g_cur[d], 1);
    g_srt[pos] = s;
}

// ==================== per-layer kernels ====================
__global__ void zero_stats_kernel() {
    int c = threadIdx.x;
    g_cs[c] = 0.0; g_css[c] = 0.0;
}

// linear: h = in @ W, plus a_s, a_d per node/head. block=128 (one node)
// use_internal: read g_hm with BN affine + relu applied on load
__global__ void lin_kernel(const float* __restrict__ xext,
                           const float* __restrict__ W,
                           const float* __restrict__ att_s,
                           const float* __restrict__ att_d,
                           int din, int use_internal) {
    int n = blockIdx.x;
    int j = threadIdx.x;
    __shared__ float xs[64];
    __shared__ float ps[4], pd[4];
    if (j < din) {
        float v;
        if (use_internal) {
            v = g_hm[n * CC + j] * g_scale[j] + g_shift[j];
            v = v > 0.f ? v : 0.f;
        } else {
            v = xext[n * din + j];
        }
        xs[j] = v;
    }
    __syncthreads();
    float acc = 0.f;
#pragma unroll 8
    for (int k = 0; k < din; k++) acc = fmaf(xs[k], W[k * HC + j], acc);
    ((float*)g_h)[n * HC + j] = acc;
    float vs = acc * att_s[j];
    float vd = acc * att_d[j];
#pragma unroll
    for (int o = 16; o; o >>= 1) {
        vs += __shfl_down_sync(0xffffffffu, vs, o);
        vd += __shfl_down_sync(0xffffffffu, vd, o);
    }
    int w = j >> 5;
    if ((j & 31) == 0) { ps[w] = vs; pd[w] = vd; }
    __syncthreads();
    if (j == 0)  { g_as[n * 2 + 0] = ps[0] + ps[1]; g_ad[n * 2 + 0] = pd[0] + pd[1]; }
    if (j == 64) { g_as[n * 2 + 1] = ps[2] + ps[3]; g_ad[n * 2 + 1] = pd[2] + pd[3]; }
}

// fused GAT aggregation: warp per node. softmax (max, sum) + weighted gather
// writes head-mean + bias to g_hm. No atomics.
__global__ void agg_kernel(const float* __restrict__ bias) {
    int node = blockIdx.x * 8 + (threadIdx.x >> 5);
    if (node >= NN) return;
    int lane = threadIdx.x & 31;
    int beg = g_row[node], end = g_row[node + 1];
    float ad0 = g_ad[node * 2], ad1 = g_ad[node * 2 + 1];

    // pass 1: segment max per head
    float m0 = -1e30f, m1 = -1e30f;
    for (int i = beg + lane; i < end; i += 32) {
        int s = g_srt[i];
        m0 = fmaxf(m0, lrelu(g_as[s * 2]     + ad0));
        m1 = fmaxf(m1, lrelu(g_as[s * 2 + 1] + ad1));
    }
#pragma unroll
    for (int o = 16; o; o >>= 1) {
        m0 = fmaxf(m0, __shfl_xor_sync(0xffffffffu, m0, o));
        m1 = fmaxf(m1, __shfl_xor_sync(0xffffffffu, m1, o));
    }

    // pass 2: sum of exp per head
    float s0 = 0.f, s1 = 0.f;
    for (int i = beg + lane; i < end; i += 32) {
        int s = g_srt[i];
        s0 += __expf(lrelu(g_as[s * 2]     + ad0) - m0);
        s1 += __expf(lrelu(g_as[s * 2 + 1] + ad1) - m1);
    }
#pragma unroll
    for (int o = 16; o; o >>= 1) {
        s0 += __shfl_xor_sync(0xffffffffu, s0, o);
        s1 += __shfl_xor_sync(0xffffffffu, s1, o);
    }

    // pass 3: weighted gather. lane -> float4 chunk; lanes 0-15 head0, 16-31 head1
    int h = lane >> 4;
    float mh  = h ? m1 : m0;
    float adh = h ? ad1 : ad0;
    float inv = 1.f / ((h ? s1 : s0) + 1e-16f);
    float4 acc = make_float4(0.f, 0.f, 0.f, 0.f);
    for (int i = beg; i < end; i++) {
        int s = g_srt[i];                       // broadcast load
        float a = __expf(lrelu(g_as[s * 2 + h] + adh) - mh) * inv;
        float4 hv = g_h[s * 32 + lane];
        acc.x = fmaf(a, hv.x, acc.x);
        acc.y = fmaf(a, hv.y, acc.y);
        acc.z = fmaf(a, hv.z, acc.z);
        acc.w = fmaf(a, hv.w, acc.w);
    }

    // head mean: lanes 0..15 combine with lanes 16..31
    float ox = __shfl_down_sync(0xffffffffu, acc.x, 16);
    float oy = __shfl_down_sync(0xffffffffu, acc.y, 16);
    float oz = __shfl_down_sync(0xffffffffu, acc.z, 16);
    float ow = __shfl_down_sync(0xffffffffu, acc.w, 16);
    if (lane < 16) {
        const float4 b4 = ((const float4*)bias)[lane];
        float4 r;
        r.x = 0.5f * (acc.x + ox) + b4.x;
        r.y = 0.5f * (acc.y + oy) + b4.y;
        r.z = 0.5f * (acc.z + oz) + b4.z;
        r.w = 0.5f * (acc.w + ow) + b4.w;
        ((float4*)g_hm)[node * 16 + lane] = r;
    }
}

// BN stats over g_hm. block = 256 = 4 node-rows x 64 channels
__global__ void bn_stats_kernel() {
    int c = threadIdx.x & 63;
    int r = threadIdx.x >> 6;
    float s1 = 0.f, s2 = 0.f;
    for (int n = blockIdx.x * 4 + r; n < NN; n += gridDim.x * 4) {
        float v = g_hm[n * CC + c];
        s1 += v; s2 += v * v;
    }
    __shared__ float sh1[256], sh2[256];
    sh1[threadIdx.x] = s1; sh2[threadIdx.x] = s2;
    __syncthreads();
    if (r == 0) {
        s1 = sh1[c] + sh1[64 + c] + sh1[128 + c] + sh1[192 + c];
        s2 = sh2[c] + sh2[64 + c] + sh2[128 + c] + sh2[192 + c];
        atomicAdd(&g_cs[c], (double)s1);
        atomicAdd(&g_css[c], (double)s2);
    }
}

__global__ void bn_fin_kernel(const float* __restrict__ gw, const float* __restrict__ be) {
    int c = threadIdx.x;
    float m = (float)(g_cs[c] / (double)NN);
    float var = (float)(g_css[c] / (double)NN) - m * m;
    var = fmaxf(var, 0.f);
    float rs = rsqrtf(var + EPS);
    float sc = rs * gw[c];
    g_scale[c] = sc;
    g_shift[c] = be[c] - m * sc;
}

// ==================== MLP heads ====================
// block = 64 threads (one node); applies BN affine + relu of layer 3 on load
__global__ void mlp_kernel(const float* __restrict__ x0,
                           const float* __restrict__ mW1, const float* __restrict__ mb1,
                           const float* __restrict__ mW2, const float* __restrict__ mb2,
                           const float* __restrict__ pW, const float* __restrict__ pb,
                           const float* __restrict__ vW, const float* __restrict__ vb,
                           float* __restrict__ out) {
    int n = blockIdx.x;
    int j = threadIdx.x;
    __shared__ float hc[72];
    __shared__ float h1[64];
    __shared__ float pl[2], pv[2];
    {
        float v = g_hm[n * CC + j] * g_scale[j] + g_shift[j];
        hc[j] = v > 0.f ? v : 0.f;
    }
    if (j < 5) hc[64 + j] = x0[n * 16 + 9 + j];
    __syncthreads();
    float a = mb1[j];
#pragma unroll
    for (int k = 0; k < 69; k++) a = fmaf(hc[k], mW1[k * 64 + j], a);
    a = a > 0.f ? a : 0.f;
    h1[j] = a;
    __syncthreads();
    float b = mb2[j];
#pragma unroll
    for (int k = 0; k < 64; k++) b = fmaf(h1[k], mW2[k * 64 + j], b);
    float lg = b * pW[j];
    float vl = b * vW[j];
#pragma unroll
    for (int o = 16; o; o >>= 1) {
        lg += __shfl_down_sync(0xffffffffu, lg, o);
        vl += __shfl_down_sync(0xffffffffu, vl, o);
    }
    int w = j >> 5;
    if ((j & 31) == 0) { pl[w] = lg; pv[w] = vl; }
    __syncthreads();
    if (j == 0) {
        out[n]      = pl[0] + pl[1] + pb[0];
        out[NN + n] = pv[0] + pv[1] + vb[0];
    }
}

// ==================== launch ====================
extern "C" void kernel_launch(void* const* d_in, const int* in_sizes, int n_in,
                              void* d_out, int out_size) {
    const float* x   = (const float*)d_in[0];
    const int*   ei  = (const int*)d_in[1];
    const int*   src = ei;
    const int*   dst = ei + EE;
    float* out = (float*)d_out;

    // ---- CSR build (per launch; deterministic) ----
    zero_cnt_kernel<<<(NN + 255) / 256, 256>>>();
    int eb = (ET + 255) / 256;
    hist_kernel<<<eb, 256>>>(dst);
    scan1_kernel<<<NB1, 1024>>>();
    scan2_kernel<<<1, 128>>>();
    scan3_kernel<<<(NN + 255) / 256, 256>>>();
    scatter_kernel<<<eb, 256>>>(src, dst);

    const int base[3] = {2, 8, 14};
    const int din[3]  = {16, 64, 64};

    for (int l = 0; l < 3; l++) {
        const float* W   = (const float*)d_in[base[l] + 0];
        const float* as_ = (const float*)d_in[base[l] + 1];
        const float* ad_ = (const float*)d_in[base[l] + 2];
        const float* b_  = (const float*)d_in[base[l] + 3];
        const float* g_  = (const float*)d_in[base[l] + 4];
        const float* be_ = (const float*)d_in[base[l] + 5];

        zero_stats_kernel<<<1, 64>>>();
        lin_kernel<<<NN, 128>>>(x, W, as_, ad_, din[l], l > 0 ? 1 : 0);
        agg_kernel<<<(NN + 7) / 8, 256>>>(b_);
        bn_stats_kernel<<<1184, 256>>>();
        bn_fin_kernel<<<1, 64>>>(g_, be_);
    }

    const float* mW1 = (const float*)d_in[20];
    const float* mb1 = (const float*)d_in[21];
    const float* mW2 = (const float*)d_in[22];
    const float* mb2 = (const float*)d_in[23];
    const float* pW  = (const float*)d_in[24];
    const float* pb  = (const float*)d_in[25];
    const float* vW  = (const float*)d_in[26];
    const float* vb  = (const float*)d_in[27];
    mlp_kernel<<<NN, 64>>>(x, mW1, mb1, mW2, mb2, pW, pb, vW, vb, out);
}